// round 8
// baseline (speedup 1.0000x reference)
#include <cuda_runtime.h>
#include <stdint.h>

#define NB 64
#define NP 8732
#define NC 81
#define NO 32
#define THRESH 0.5f
#define NPR 3
#define MCH 16
#define MTH 256
#define PCHUNK ((NP + MCH - 1) / MCH)   // 546

// ---------------- device scratch (zero-init, self-resetting) ----------------
__device__ unsigned long long g_key[NB * NO];   // (iou_bits<<32)|(0x7fffffff-p); 0 = empty
__device__ unsigned char g_obj[NB * NP];
__device__ unsigned char g_lab[NB * NP];
__device__ float g_ceneg[NB * NP];
__device__ int   g_npos[NB];
__device__ int   g_done[NB];
__device__ int   g_hbdone;
__device__ float g_loc_sum, g_pos_sum, g_hard_sum;
__device__ int   g_npos_total;

__device__ __forceinline__ float loc_term(const float4 pl, const float4 pr,
                                          float bx0, float by0, float bx1, float by1)
{
    const float cx = (bx0 + bx1) * 0.5f, cy = (by0 + by1) * 0.5f;
    const float w = bx1 - bx0, h = by1 - by0;
    const float g0 = (cx - pr.x) / (pr.z * 0.1f);
    const float g1 = (cy - pr.y) / (pr.w * 0.1f);
    const float g2 = logf(w / pr.z) * 5.0f;
    const float g3 = logf(h / pr.w) * 5.0f;
    return fabsf(pl.x - g0) + fabsf(pl.y - g1) + fabsf(pl.z - g2) + fabsf(pl.w - g3);
}

// ---------------- kernel 1: matching + loc loss + force-fix ----------------
// lane = object (NO == 32), warp = one prior per step. Per-object argmax is
// register-local; per-prior argmax is one REDUX + BALLOT per prior.
__global__ __launch_bounds__(MTH) void k_match(
    const float4* __restrict__ priors4,   // [P] cxcy
    const float*  __restrict__ boxes,     // [B,O,4] xy
    const float4* __restrict__ predloc4,  // [B*P]
    const int*    __restrict__ labels_i32)
{
    __shared__ float4 s_box[NO];
    __shared__ unsigned long long s_key[NO];
    __shared__ float s_rf[MTH / 32];
    __shared__ int   s_ri[MTH / 32];
    __shared__ int   s_last;

    const int b = blockIdx.y, chunk = blockIdx.x, tid = threadIdx.x;
    const int lane = tid & 31, warp = tid >> 5;
    const bool lab64 = (labels_i32[1] == 0);

    // lane-owned object, all in registers
    const float4 bb = *(const float4*)(boxes + (b*NO + lane) * 4);
    const float ba = (bb.z - bb.x) * (bb.w - bb.y);
    const int mylab = lab64 ? labels_i32[(b*NO+lane)*2] : labels_i32[b*NO+lane];

    if (tid < NO) { s_key[tid] = 0ull; s_box[tid] = bb; }  // warp 0: lane==tid
    __syncthreads();

    const int p0 = chunk * PCHUNK;
    const int p1 = (p0 + PCHUNK < NP) ? p0 + PCHUNK : NP;
    float locsum = 0.f; int npos = 0;
    float objBest = -1.f; int objP = 0;    // per-lane = per-object tracker

    for (int pa = p0 + warp; pa < p1; pa += 16) {
        #pragma unroll
        for (int u = 0; u < 2; ++u) {
            const int p = pa + u * 8;
            if (p < p1) {                                    // warp-uniform
                const float4 pr = __ldg(priors4 + p);        // broadcast LDG
                const float px0 = pr.x - pr.z * 0.5f, py0 = pr.y - pr.w * 0.5f;
                const float px1 = pr.x + pr.z * 0.5f, py1 = pr.y + pr.w * 0.5f;
                const float iw = fmaxf(fminf(bb.z, px1) - fmaxf(bb.x, px0), 0.f);
                const float ih = fmaxf(fminf(bb.w, py1) - fmaxf(bb.y, py0), 0.f);
                const float inter = iw * ih;
                const float iou = __fdividef(inter, ba + pr.z * pr.w - inter);
                if (iou > objBest) { objBest = iou; objP = p; }   // regs only
                const unsigned ib = __float_as_uint(iou);         // iou>=0: monotonic
                const unsigned mx = __reduce_max_sync(0xffffffffu, ib);
                const unsigned mk = __ballot_sync(0xffffffffu, ib == mx);
                if (lane == __ffs(mk) - 1) {                      // first-max object
                    const int lab = (iou < THRESH) ? 0 : mylab;
                    g_lab[b*NP+p] = (unsigned char)lab;
                    g_obj[b*NP+p] = (unsigned char)lane;
                    if (lab != 0) {
                        ++npos;
                        locsum += loc_term(predloc4[b*NP+p], pr, bb.x, bb.y, bb.z, bb.w);
                    }
                }
            }
        }
    }

    // combine per-object trackers (one key per lane per warp)
    {
        const unsigned long long key =
            ((unsigned long long)__float_as_uint(fmaxf(objBest, 0.f)) << 32) |
            (unsigned)(0x7fffffff - objP);
        atomicMax(&s_key[lane], key);
    }

    // block reduce npos/locsum
    #pragma unroll
    for (int off = 16; off; off >>= 1) {
        locsum += __shfl_xor_sync(0xffffffffu, locsum, off);
        npos   += __shfl_xor_sync(0xffffffffu, npos, off);
    }
    if (lane == 0) { s_rf[warp] = locsum; s_ri[warp] = npos; }
    __syncthreads();
    if (tid < NO) atomicMax(&g_key[b*NO+tid], s_key[tid]);
    if (tid == 0) {
        float f = 0.f; int c = 0;
        #pragma unroll
        for (int i = 0; i < MTH/32; ++i) { f += s_rf[i]; c += s_ri[i]; }
        if (f != 0.f) atomicAdd(&g_loc_sum, f);
        if (c) { atomicAdd(&g_npos[b], c); atomicAdd(&g_npos_total, c); }
        __threadfence();
        const int old = atomicAdd(&g_done[b], 1);
        s_last = (old == MCH - 1);
    }
    __syncthreads();

    // last CTA of this batch applies the <=NO force-match corrections
    if (s_last && tid < 32) {
        __threadfence();
        const unsigned long long key = g_key[b*NO + lane];
        g_key[b*NO + lane] = 0ull;                 // reset for next replay
        if (lane == 0) g_done[b] = 0;
        const int p = 0x7fffffff - (int)(unsigned)(key & 0xffffffffull);
        const unsigned mm = __match_any_sync(0xffffffffu, p);
        float dloc = 0.f; int dnp = 0;
        if ((unsigned)p < NP && lane == 31 - __clz(mm)) {  // last .at[].set wins -> highest o
            const int oldlab = g_lab[b*NP+p];
            g_lab[b*NP+p] = (unsigned char)mylab;
            const float4 pr = priors4[p];
            const float4 pl = predloc4[b*NP+p];
            dloc = loc_term(pl, pr, bb.x, bb.y, bb.z, bb.w);
            if (oldlab != 0) {
                const int oo = g_obj[b*NP+p];
                const float4 ob = s_box[oo];
                dloc -= loc_term(pl, pr, ob.x, ob.y, ob.z, ob.w);
            } else {
                dnp = 1;
            }
        }
        #pragma unroll
        for (int off = 16; off; off >>= 1) {
            dloc += __shfl_xor_sync(0xffffffffu, dloc, off);
            dnp  += __shfl_xor_sync(0xffffffffu, dnp, off);
        }
        if (lane == 0) {
            if (dloc != 0.f) atomicAdd(&g_loc_sum, dloc);
            if (dnp) { atomicAdd(&g_npos[b], dnp); atomicAdd(&g_npos_total, dnp); }
        }
    }
}

// ---------------- kernel 2: cross entropy, 4 rows per warp ----------------
__global__ __launch_bounds__(256) void k_ce(const float* __restrict__ scores)
{
    __shared__ float s_pos;
    const int tid = threadIdx.x, lane = tid & 31;
    if (tid == 0) s_pos = 0.f;
    __syncthreads();

    const int gw = (int)((blockIdx.x * blockDim.x + tid) >> 5);
    const int r0 = gw * 4;
    if (r0 < NB * NP) {
        float x0[4], x1[4], x2[4];
        const bool hi = (lane < NC - 64);
        #pragma unroll
        for (int r = 0; r < 4; ++r) {
            const float* rp = scores + (size_t)(r0 + r) * NC;
            x0[r] = rp[lane];
            x1[r] = rp[lane + 32];
            x2[r] = hi ? rp[lane + 64] : -3.0e38f;
        }
        float m[4], s[4];
        #pragma unroll
        for (int r = 0; r < 4; ++r) m[r] = fmaxf(fmaxf(x0[r], x1[r]), x2[r]);
        #pragma unroll
        for (int off = 16; off; off >>= 1) {
            #pragma unroll
            for (int r = 0; r < 4; ++r)
                m[r] = fmaxf(m[r], __shfl_xor_sync(0xffffffffu, m[r], off));
        }
        #pragma unroll
        for (int r = 0; r < 4; ++r)
            s[r] = __expf(x0[r]-m[r]) + __expf(x1[r]-m[r]) + (hi ? __expf(x2[r]-m[r]) : 0.f);
        #pragma unroll
        for (int off = 16; off; off >>= 1) {
            #pragma unroll
            for (int r = 0; r < 4; ++r)
                s[r] += __shfl_xor_sync(0xffffffffu, s[r], off);
        }
        const uchar4 lv = *(const uchar4*)(g_lab + r0);
        const int l[4] = {lv.x, lv.y, lv.z, lv.w};
        float ceneg[4]; float pp = 0.f;
        #pragma unroll
        for (int r = 0; r < 4; ++r) {
            float sl;
            if (l[r] < 32)      sl = __shfl_sync(0xffffffffu, x0[r], l[r]);
            else if (l[r] < 64) sl = __shfl_sync(0xffffffffu, x1[r], l[r] - 32);
            else                sl = __shfl_sync(0xffffffffu, x2[r], l[r] - 64);
            const float ce = m[r] + __logf(s[r]) - sl;
            if (l[r] != 0) { pp += ce; ceneg[r] = 0.f; }
            else           { ceneg[r] = ce; }
        }
        if (lane == 0) {
            *(float4*)(g_ceneg + r0) = make_float4(ceneg[0], ceneg[1], ceneg[2], ceneg[3]);
            if (pp != 0.f) atomicAdd(&s_pos, pp);
        }
    }
    __syncthreads();
    if (tid == 0 && s_pos != 0.f) atomicAdd(&g_pos_sum, s_pos);
}

// ---------------- kernel 3: exact top-k via radix select (1024 thr, warp scan) ----------------
__global__ __launch_bounds__(1024) void k_hardneg(float* __restrict__ out)
{
    __shared__ float s_ce[NP];
    __shared__ int s_cnt[256];
    __shared__ unsigned sh_prefix;
    __shared__ int sh_rem, sh_k;
    __shared__ float s_r[32];

    const int b = blockIdx.x, tid = threadIdx.x, nt = 1024, lane = tid & 31;
    for (int i = tid; i < NP / 4; i += nt)
        *(float4*)(s_ce + i * 4) = *(const float4*)(g_ceneg + b*NP + i * 4);
    if (tid == 0) {
        sh_k = NPR * g_npos[b];
        g_npos[b] = 0;                 // reset for next replay
        sh_prefix = 0u; sh_rem = sh_k;
    }
    __syncthreads();
    const int k = sh_k;

    if (k > 0 && k < NP) {
        for (int shift = 24; shift >= 0; shift -= 8) {
            const unsigned pref = sh_prefix;
            const int rem = sh_rem;
            const unsigned hm = (shift == 24) ? 0u : (0xffffffffu << (shift + 8));
            if (tid < 256) s_cnt[tid] = 0;
            __syncthreads();
            for (int base = 0; base < NP; base += nt) {
                const int p = base + tid;
                unsigned bin = 0xffffffffu;
                if (p < NP) {
                    const unsigned bits = __float_as_uint(s_ce[p]);
                    if ((bits & hm) == pref) bin = (bits >> shift) & 255u;
                }
                const unsigned mm = __match_any_sync(0xffffffffu, bin);
                if (bin != 0xffffffffu && lane == (unsigned)(__ffs(mm) - 1))
                    atomicAdd(&s_cnt[bin], __popc(mm));
            }
            __syncthreads();
            // suffix scan of 256 bins by warp 0: lane owns 8 bins, register scan
            if (tid < 32) {
                int c[8]; int tot = 0;
                #pragma unroll
                for (int q = 0; q < 8; ++q) { c[q] = s_cnt[lane*8+q]; tot += c[q]; }
                int inc = tot;
                #pragma unroll
                for (int off = 1; off < 32; off <<= 1) {
                    const int v = __shfl_down_sync(0xffffffffu, inc, off);
                    if (lane + off < 32) inc += v;
                }
                int run = inc - tot;              // exclusive suffix of higher segments
                #pragma unroll
                for (int q = 7; q >= 0; --q) { run += c[q]; s_cnt[lane*8+q] = run; }
            }
            __syncthreads();
            if (tid < 256) {
                const int ge = s_cnt[tid];
                const int gt = (tid < 255) ? s_cnt[tid + 1] : 0;
                if (ge >= rem && gt < rem) {
                    sh_rem = rem - gt;
                    sh_prefix = pref | ((unsigned)tid << shift);
                }
            }
            __syncthreads();
        }
        const float kth = __uint_as_float(sh_prefix);
        const int rem = sh_rem;
        float acc = 0.f;
        for (int p = tid; p < NP; p += nt) { const float v = s_ce[p]; if (v > kth) acc += v; }
        #pragma unroll
        for (int off = 16; off; off >>= 1) acc += __shfl_xor_sync(0xffffffffu, acc, off);
        if (lane == 0) s_r[tid >> 5] = acc;
        __syncthreads();
        if (tid == 0) {
            float t = (float)rem * kth;
            #pragma unroll
            for (int i = 0; i < 32; ++i) t += s_r[i];
            atomicAdd(&g_hard_sum, t);
        }
    } else if (k >= NP) {
        float acc = 0.f;
        for (int p = tid; p < NP; p += nt) acc += s_ce[p];
        #pragma unroll
        for (int off = 16; off; off >>= 1) acc += __shfl_xor_sync(0xffffffffu, acc, off);
        if (lane == 0) s_r[tid >> 5] = acc;
        __syncthreads();
        if (tid == 0) {
            float t = 0.f;
            #pragma unroll
            for (int i = 0; i < 32; ++i) t += s_r[i];
            atomicAdd(&g_hard_sum, t);
        }
    }

    // fused finalize: last CTA computes the loss and resets accumulators
    __syncthreads();
    if (tid == 0) {
        __threadfence();
        const int old = atomicAdd(&g_hbdone, 1);
        if (old == NB - 1) {
            __threadfence();
            const float np = (float)g_npos_total;
            out[0] = (g_hard_sum + g_pos_sum) / np + g_loc_sum / (np * 4.0f);
            g_loc_sum = 0.f; g_pos_sum = 0.f; g_hard_sum = 0.f;
            g_npos_total = 0; g_hbdone = 0;
        }
    }
}

// ---------------- launch ----------------
extern "C" void kernel_launch(void* const* d_in, const int* in_sizes, int n_in,
                              void* d_out, int out_size)
{
    const float* pred_locs   = (const float*)d_in[0];
    const float* pred_scores = (const float*)d_in[1];
    const float* boxes       = (const float*)d_in[2];
    const int*   labels      = (const int*)d_in[3];
    const float* priors      = (const float*)d_in[4];
    float* out = (float*)d_out;

    dim3 mg(MCH, NB);
    k_match<<<mg, MTH>>>((const float4*)priors, boxes, (const float4*)pred_locs, labels);
    const int warps4 = (NB * NP + 3) / 4;
    k_ce<<<(warps4 * 32 + 255) / 256, 256>>>(pred_scores);
    k_hardneg<<<NB, 1024>>>(out);
}

// round 9
// speedup vs baseline: 1.3400x; 1.3400x over previous
#include <cuda_runtime.h>
#include <stdint.h>

#define NB 64
#define NP 8732
#define NC 81
#define NO 32
#define THRESH 0.5f
#define NPR 3
#define MCH 16
#define MTH 256
#define PCHUNK ((NP + MCH - 1) / MCH)   // 546
#define CEROWS 128                       // rows per k_ce CTA (558848/128 = 4366 exact)

// ---------------- device scratch (zero-init, self-resetting) ----------------
__device__ unsigned long long g_key[NB * NO];   // (iou_bits<<32)|(0x7fffffff-p); 0 = empty
__device__ unsigned char g_obj[NB * NP];
__device__ unsigned char g_lab[NB * NP];
__device__ float g_ceneg[NB * NP];
__device__ int   g_npos[NB];
__device__ int   g_done[NB];
__device__ int   g_hbdone;
__device__ float g_loc_sum, g_pos_sum, g_hard_sum;
__device__ int   g_npos_total;

__device__ __forceinline__ float loc_term(const float4 pl, const float4 pr,
                                          float bx0, float by0, float bx1, float by1)
{
    const float cx = (bx0 + bx1) * 0.5f, cy = (by0 + by1) * 0.5f;
    const float w = bx1 - bx0, h = by1 - by0;
    const float g0 = (cx - pr.x) / (pr.z * 0.1f);
    const float g1 = (cy - pr.y) / (pr.w * 0.1f);
    const float g2 = logf(w / pr.z) * 5.0f;
    const float g3 = logf(h / pr.w) * 5.0f;
    return fabsf(pl.x - g0) + fabsf(pl.y - g1) + fabsf(pl.z - g2) + fabsf(pl.w - g3);
}

// ---------------- kernel 1: matching + loc loss + force-fix (R4 structure, 39 us) ----------------
__global__ __launch_bounds__(MTH) void k_match(
    const float4* __restrict__ priors4,   // [P] cxcy
    const float*  __restrict__ boxes,     // [B,O,4] xy
    const float4* __restrict__ predloc4,  // [B*P]
    const int*    __restrict__ labels_i32)
{
    __shared__ float4 s_box[NO];          // (x0,y0,x1,y1)
    __shared__ float  s_ba[NO];
    __shared__ int s_lab[NO];
    __shared__ unsigned long long s_key[NO];
    __shared__ float s_rf[MTH / 32];
    __shared__ int   s_ri[MTH / 32];
    __shared__ int   s_last;

    const int b = blockIdx.y, chunk = blockIdx.x, tid = threadIdx.x;
    const bool lab64 = (labels_i32[1] == 0);
    if (tid < NO) {
        const float x0 = boxes[(b*NO+tid)*4+0], y0 = boxes[(b*NO+tid)*4+1];
        const float x1 = boxes[(b*NO+tid)*4+2], y1 = boxes[(b*NO+tid)*4+3];
        s_box[tid] = make_float4(x0, y0, x1, y1);
        s_ba[tid] = (x1 - x0) * (y1 - y0);
        s_lab[tid] = lab64 ? labels_i32[(b*NO+tid)*2] : labels_i32[b*NO+tid];
        s_key[tid] = 0ull;
    }
    __syncthreads();

    const int p0 = chunk * PCHUNK;
    const int p1 = (p0 + PCHUNK < NP) ? p0 + PCHUNK : NP;
    float locsum = 0.f; int npos = 0;

    for (int p = p0 + tid; p < p1; p += MTH) {
        const float4 pr = priors4[p];
        const float px0 = pr.x - pr.z * 0.5f, py0 = pr.y - pr.w * 0.5f;
        const float px1 = pr.x + pr.z * 0.5f, py1 = pr.y + pr.w * 0.5f;
        const float parea = (px1 - px0) * (py1 - py0);
        const unsigned lowp = (unsigned)(0x7fffffff - p);
        float best = 0.f; int bi = 0;
        #pragma unroll 8
        for (int o = 0; o < NO; ++o) {
            const float4 bx = s_box[o];
            const float iw = fminf(bx.z, px1) - fmaxf(bx.x, px0);
            const float ih = fminf(bx.w, py1) - fmaxf(bx.y, py0);
            if (iw > 0.f && ih > 0.f) {           // ~82% of pairs skip everything
                const float inter = iw * ih;
                const float iou = __fdividef(inter, s_ba[o] + parea - inter);
                if (iou > best) { best = iou; bi = o; }   // strict > -> first max
                const unsigned long long key =
                    ((unsigned long long)__float_as_uint(iou) << 32) | lowp;
                if (key > s_key[o]) atomicMax(&s_key[o], key);  // monotonic
            }
        }
        const int lab = (best < THRESH) ? 0 : s_lab[bi];
        g_lab[b*NP+p] = (unsigned char)lab;
        g_obj[b*NP+p] = (unsigned char)bi;
        if (lab != 0) {
            ++npos;
            const float4 bb = s_box[bi];
            locsum += loc_term(predloc4[b*NP+p], pr, bb.x, bb.y, bb.z, bb.w);
        }
    }
    __syncthreads();
    // zero-overlap objects: reference argmax -> prior 0; inject that key if none seen
    if (tid < NO) {
        const unsigned long long kz = s_key[tid] ? s_key[tid] : 0x7fffffffull;
        atomicMax(&g_key[b*NO+tid], kz);
    }

    // block reduce npos/locsum
    #pragma unroll
    for (int off = 16; off; off >>= 1) {
        locsum += __shfl_xor_sync(0xffffffffu, locsum, off);
        npos   += __shfl_xor_sync(0xffffffffu, npos, off);
    }
    if ((tid & 31) == 0) { s_rf[tid>>5] = locsum; s_ri[tid>>5] = npos; }
    __syncthreads();
    if (tid == 0) {
        float f = 0.f; int c = 0;
        #pragma unroll
        for (int i = 0; i < MTH/32; ++i) { f += s_rf[i]; c += s_ri[i]; }
        if (f != 0.f) atomicAdd(&g_loc_sum, f);
        if (c) { atomicAdd(&g_npos[b], c); atomicAdd(&g_npos_total, c); }
        __threadfence();
        const int old = atomicAdd(&g_done[b], 1);
        s_last = (old == MCH - 1);
    }
    __syncthreads();

    // last CTA of this batch applies the <=NO force-match corrections
    if (s_last && tid < 32) {
        __threadfence();
        const int lane = tid;
        const unsigned long long key = g_key[b*NO + lane];
        g_key[b*NO + lane] = 0ull;                 // reset for next replay
        if (lane == 0) g_done[b] = 0;
        const int p = 0x7fffffff - (int)(unsigned)(key & 0xffffffffull);
        const unsigned mm = __match_any_sync(0xffffffffu, p);
        float dloc = 0.f; int dnp = 0;
        if ((unsigned)p < NP && lane == 31 - __clz(mm)) {  // last .at[].set wins -> highest o
            const int oldlab = g_lab[b*NP+p];
            g_lab[b*NP+p] = (unsigned char)s_lab[lane];
            const float4 pr = priors4[p];
            const float4 pl = predloc4[b*NP+p];
            const float4 bb = s_box[lane];
            dloc = loc_term(pl, pr, bb.x, bb.y, bb.z, bb.w);
            if (oldlab != 0) {
                const int oo = g_obj[b*NP+p];
                const float4 ob = s_box[oo];
                dloc -= loc_term(pl, pr, ob.x, ob.y, ob.z, ob.w);
            } else {
                dnp = 1;
            }
        }
        #pragma unroll
        for (int off = 16; off; off >>= 1) {
            dloc += __shfl_xor_sync(0xffffffffu, dloc, off);
            dnp  += __shfl_xor_sync(0xffffffffu, dnp, off);
        }
        if (lane == 0) {
            if (dloc != 0.f) atomicAdd(&g_loc_sum, dloc);
            if (dnp) { atomicAdd(&g_npos[b], dnp); atomicAdd(&g_npos_total, dnp); }
        }
    }
}

// ---------------- kernel 2: cross entropy — smem-staged, thread-per-row ----------------
// CTA: 128 threads, 128 rows. Coalesced float4 GMEM -> smem, then each thread
// reduces its own row from smem (stride 81 mod 32 = 17 -> conflict-free).
__global__ __launch_bounds__(CEROWS) void k_ce(const float* __restrict__ scores)
{
    __shared__ float s[CEROWS * NC];     // 41472 B
    __shared__ float s_pos;
    const int tid = threadIdx.x;
    const size_t base = (size_t)blockIdx.x * (CEROWS * NC);

    const float4* src = (const float4*)(scores + base);   // base % 4 == 0
    float4* dst = (float4*)s;
    #pragma unroll 5
    for (int i = tid; i < CEROWS * NC / 4; i += CEROWS) dst[i] = src[i];
    if (tid == 0) s_pos = 0.f;
    __syncthreads();

    const int row = blockIdx.x * CEROWS + tid;
    const float* r = s + tid * NC;

    // max with 4 accumulators (break dependence chain)
    float m0 = r[0], m1 = r[1], m2 = r[2], m3 = r[3];
    #pragma unroll
    for (int i = 4; i + 3 < NC; i += 4) {
        m0 = fmaxf(m0, r[i]); m1 = fmaxf(m1, r[i+1]);
        m2 = fmaxf(m2, r[i+2]); m3 = fmaxf(m3, r[i+3]);
    }
    float m = fmaxf(fmaxf(m0, m1), fmaxf(m2, m3));
    m = fmaxf(m, r[NC - 1]);   // 81 = 4 + 76 + 1

    // exp-sum with 4 accumulators
    float a0 = 0.f, a1 = 0.f, a2 = 0.f, a3 = 0.f;
    #pragma unroll
    for (int i = 0; i + 3 < NC; i += 4) {
        a0 += __expf(r[i] - m);   a1 += __expf(r[i+1] - m);
        a2 += __expf(r[i+2] - m); a3 += __expf(r[i+3] - m);
    }
    float sum = (a0 + a1) + (a2 + a3) + __expf(r[NC - 1] - m);

    const int lab = g_lab[row];
    const float ce = m + __logf(sum) - r[lab];
    if (lab != 0) {
        g_ceneg[row] = 0.f;
        atomicAdd(&s_pos, ce);     // positives ~2% of rows
    } else {
        g_ceneg[row] = ce;
    }
    __syncthreads();
    if (tid == 0 && s_pos != 0.f) atomicAdd(&g_pos_sum, s_pos);
}

// ---------------- kernel 3: exact top-k via radix select (1024 thr, warp scan) ----------------
__global__ __launch_bounds__(1024) void k_hardneg(float* __restrict__ out)
{
    __shared__ float s_ce[NP];
    __shared__ int s_cnt[256];
    __shared__ unsigned sh_prefix;
    __shared__ int sh_rem, sh_k;
    __shared__ float s_r[32];

    const int b = blockIdx.x, tid = threadIdx.x, nt = 1024, lane = tid & 31;
    for (int i = tid; i < NP / 4; i += nt)
        *(float4*)(s_ce + i * 4) = *(const float4*)(g_ceneg + b*NP + i * 4);
    if (tid == 0) {
        sh_k = NPR * g_npos[b];
        g_npos[b] = 0;                 // reset for next replay
        sh_prefix = 0u; sh_rem = sh_k;
    }
    __syncthreads();
    const int k = sh_k;

    if (k > 0 && k < NP) {
        for (int shift = 24; shift >= 0; shift -= 8) {
            const unsigned pref = sh_prefix;
            const int rem = sh_rem;
            const unsigned hm = (shift == 24) ? 0u : (0xffffffffu << (shift + 8));
            if (tid < 256) s_cnt[tid] = 0;
            __syncthreads();
            for (int base = 0; base < NP; base += nt) {
                const int p = base + tid;
                unsigned bin = 0xffffffffu;
                if (p < NP) {
                    const unsigned bits = __float_as_uint(s_ce[p]);
                    if ((bits & hm) == pref) bin = (bits >> shift) & 255u;
                }
                const unsigned mm = __match_any_sync(0xffffffffu, bin);
                if (bin != 0xffffffffu && lane == (unsigned)(__ffs(mm) - 1))
                    atomicAdd(&s_cnt[bin], __popc(mm));
            }
            __syncthreads();
            // suffix scan of 256 bins by warp 0: lane owns 8 bins, register scan
            if (tid < 32) {
                int c[8]; int tot = 0;
                #pragma unroll
                for (int q = 0; q < 8; ++q) { c[q] = s_cnt[lane*8+q]; tot += c[q]; }
                int inc = tot;
                #pragma unroll
                for (int off = 1; off < 32; off <<= 1) {
                    const int v = __shfl_down_sync(0xffffffffu, inc, off);
                    if (lane + off < 32) inc += v;
                }
                int run = inc - tot;              // exclusive suffix of higher segments
                #pragma unroll
                for (int q = 7; q >= 0; --q) { run += c[q]; s_cnt[lane*8+q] = run; }
            }
            __syncthreads();
            if (tid < 256) {
                const int ge = s_cnt[tid];
                const int gt = (tid < 255) ? s_cnt[tid + 1] : 0;
                if (ge >= rem && gt < rem) {
                    sh_rem = rem - gt;
                    sh_prefix = pref | ((unsigned)tid << shift);
                }
            }
            __syncthreads();
        }
        const float kth = __uint_as_float(sh_prefix);
        const int rem = sh_rem;
        float acc = 0.f;
        for (int p = tid; p < NP; p += nt) { const float v = s_ce[p]; if (v > kth) acc += v; }
        #pragma unroll
        for (int off = 16; off; off >>= 1) acc += __shfl_xor_sync(0xffffffffu, acc, off);
        if (lane == 0) s_r[tid >> 5] = acc;
        __syncthreads();
        if (tid == 0) {
            float t = (float)rem * kth;
            #pragma unroll
            for (int i = 0; i < 32; ++i) t += s_r[i];
            atomicAdd(&g_hard_sum, t);
        }
    } else if (k >= NP) {
        float acc = 0.f;
        for (int p = tid; p < NP; p += nt) acc += s_ce[p];
        #pragma unroll
        for (int off = 16; off; off >>= 1) acc += __shfl_xor_sync(0xffffffffu, acc, off);
        if (lane == 0) s_r[tid >> 5] = acc;
        __syncthreads();
        if (tid == 0) {
            float t = 0.f;
            #pragma unroll
            for (int i = 0; i < 32; ++i) t += s_r[i];
            atomicAdd(&g_hard_sum, t);
        }
    }

    // fused finalize: last CTA computes the loss and resets accumulators
    __syncthreads();
    if (tid == 0) {
        __threadfence();
        const int old = atomicAdd(&g_hbdone, 1);
        if (old == NB - 1) {
            __threadfence();
            const float np = (float)g_npos_total;
            out[0] = (g_hard_sum + g_pos_sum) / np + g_loc_sum / (np * 4.0f);
            g_loc_sum = 0.f; g_pos_sum = 0.f; g_hard_sum = 0.f;
            g_npos_total = 0; g_hbdone = 0;
        }
    }
}

// ---------------- launch ----------------
extern "C" void kernel_launch(void* const* d_in, const int* in_sizes, int n_in,
                              void* d_out, int out_size)
{
    const float* pred_locs   = (const float*)d_in[0];
    const float* pred_scores = (const float*)d_in[1];
    const float* boxes       = (const float*)d_in[2];
    const int*   labels      = (const int*)d_in[3];
    const float* priors      = (const float*)d_in[4];
    float* out = (float*)d_out;

    dim3 mg(MCH, NB);
    k_match<<<mg, MTH>>>((const float4*)priors, boxes, (const float4*)pred_locs, labels);
    k_ce<<<(NB * NP) / CEROWS, CEROWS>>>(pred_scores);
    k_hardneg<<<NB, 1024>>>(out);
}